// round 11
// baseline (speedup 1.0000x reference)
#include <cuda_runtime.h>

// ComponentWiseSpline: rational-quadratic spline flow, forward + log|det J|.
// B=65536 rows, D=128 dims, K=8 interior bins.
// R11: spill-free high occupancy: (256,5) -> reg cap 51, grid 740=148x5.
//      9-slot table (identity slot 0 shared by both tails via -8 FFMA trick),
//      sThr/sPart smem overlay (42.8KB -> 5 blocks/SM), 3-step butterfly.

#define BB 65536
#define DD 128
#define KK 8
#define NSLOT 9                          // identity | 8 interior
#define NPAIRS (BB / 2)                  // 32768 row-pairs
#define BLOCK 256
#define TEAMS 2                          // 4-warp teams per block
#define GRIDB 740                        // 148 SMs * 5 blocks
#define NSP (GRIDB * TEAMS)              // 1480 row-pair streams
#define MAXP ((NPAIRS + NSP - 1) / NSP)  // 23

// overlay: thresholds (staging) and per-warp partials never live simultaneously
#define AUXN (TEAMS * 4 * MAXP * 2 * 4)  // 1472 floats (> 9*128 = 1152)
#define PART(t, w, pi, r, q) sAux[((((t) * 4 + (w)) * MAXP + (pi)) * 2 + (r)) * 4 + (q)]

__device__ __forceinline__ float fsetge(float a, float b) {
    float r;
    asm("set.ge.f32.f32 %0, %1, %2;" : "=f"(r) : "f"(a), "f"(b));
    return r;
}

__global__ void __launch_bounds__(BLOCK, 5)
spline_kernel(const float* __restrict__ x,
              const float* __restrict__ uw,
              const float* __restrict__ uh,
              const float* __restrict__ ud,
              float* __restrict__ uout,
              float* __restrict__ ldout) {
    __shared__ float4 sTA[NSLOT * DD];   // 18 KB {invW, -cw*invW, cumH, H}
    __shared__ float4 sTB[NSLOT * DD];   // 18 KB {delta, d0, d1, e}
    __shared__ float  sAux[AUXN];        // 5.75 KB: thresholds, then partials

    const int tid  = threadIdx.x;
    const int lane = tid & 31;
    const int warp = tid >> 5;       // 0..7
    const int team = warp >> 2;      // 0..1
    const int wslot = warp & 3;      // 0..3
    const int d = (wslot << 5) + lane;

    // ---- per-block table build: thread dd (<128) builds dim dd ----
    if (tid < DD) {
        const float BOUND = 3.0f;
        const float MINW = 1e-3f, MINH = 1e-3f, MIND = 1e-3f, EPS = 1e-6f;
        const int dd = tid;

        float w[KK], h[KK];
        float m = -1e30f;
        #pragma unroll
        for (int k = 0; k < KK; k++) { w[k] = uw[dd * KK + k]; m = fmaxf(m, w[k]); }
        float s = 0.f;
        #pragma unroll
        for (int k = 0; k < KK; k++) { w[k] = expf(w[k] - m); s += w[k]; }
        float invs = 1.0f / s;
        #pragma unroll
        for (int k = 0; k < KK; k++) w[k] = MINW + (1.0f - MINW * KK) * (w[k] * invs);

        m = -1e30f;
        #pragma unroll
        for (int k = 0; k < KK; k++) { h[k] = uh[dd * KK + k]; m = fmaxf(m, h[k]); }
        s = 0.f;
        #pragma unroll
        for (int k = 0; k < KK; k++) { h[k] = expf(h[k] - m); s += h[k]; }
        invs = 1.0f / s;
        #pragma unroll
        for (int k = 0; k < KK; k++) h[k] = MINH + (1.0f - MINH * KK) * (h[k] * invs);

        float cw[KK + 1], ch[KK + 1];
        cw[0] = -BOUND; ch[0] = -BOUND;
        float accw = 0.f, acch = 0.f;
        #pragma unroll
        for (int k = 1; k < KK; k++) {
            accw += w[k - 1]; cw[k] = fmaf(2.0f * BOUND, accw, -BOUND);
            acch += h[k - 1]; ch[k] = fmaf(2.0f * BOUND, acch, -BOUND);
        }
        cw[KK] = BOUND; ch[KK] = BOUND;

        float dv[KK + 1];
        dv[0] = 1.0f - MIND; dv[KK] = 1.0f - MIND;
        #pragma unroll
        for (int k = 1; k < KK; k++) {
            float v = ud[dd * (KK - 1) + (k - 1)];
            dv[k] = MIND + fmaxf(v, 0.0f) + log1pf(expf(-fabsf(v)));
        }

        // interior bins k -> slot k+1 (slots 1..8)
        #pragma unroll
        for (int k = 0; k < KK; k++) {
            float W = cw[k + 1] - cw[k];
            float H = ch[k + 1] - ch[k];
            float invW = 1.0f / W;
            float del  = H * invW;
            sTA[(k + 1) * DD + dd] = make_float4(invW, -cw[k] * invW, ch[k], H);
            sTB[(k + 1) * DD + dd] = make_float4(del, dv[k], dv[k + 1],
                                                 dv[k] + dv[k + 1] - 2.0f * del);
        }
        // identity slot 0 (both tails): u = x, lad = 0
        sTA[0 * DD + dd] = make_float4(1.0f, 0.0f, 0.0f, 1.0f);
        sTB[0 * DD + dd] = make_float4(1.0f, 1.0f, 1.0f, 0.0f);

        // thresholds into overlay region
        sAux[0 * DD + dd] = -3.0f;
        #pragma unroll
        for (int t = 1; t < 8; t++) sAux[t * DD + dd] = cw[t] + EPS;
        sAux[8 * DD + dd] = __int_as_float(0x40400001);   // nextafter(3.0f)
    }
    __syncthreads();

    // ---- this lane's 9 thresholds into registers ----
    float thr[9];
    #pragma unroll
    for (int j = 0; j < 9; j++) thr[j] = sAux[j * DD + d];
    __syncthreads();    // overlay handoff: thresholds read, partials may now write

    const int S = blockIdx.x * TEAMS + team;        // stream id, 0..NSP-1
    const int cnt = (NPAIRS - S + NSP - 1) / NSP;   // 22 or 23 pairs
    const size_t STEP = (size_t)NSP * 256;

    const float* px = x + (size_t)S * 256 + d;
    float*       pu = uout + (size_t)S * 256 + d;
    float xa = px[0];
    float xb = px[DD];

    for (int pi = 0; pi < cnt; pi++) {
        float xa2, xb2;
        if (pi < cnt - 1) {
            xa2 = __ldg(px + STEP);
            xb2 = __ldg(px + STEP + DD);
        }

        float lads[2];
        float xin[2] = {xa, xb};
        #pragma unroll
        for (int e = 0; e < 2; e++) {
            const float xv = xin[e];
            // slot = 1 + bin for interior; 0 for both tails (via -8 on thr[8])
            float s0 = fsetge(xv, thr[0]) + fsetge(xv, thr[1]);
            float s1 = fsetge(xv, thr[2]) + fsetge(xv, thr[3]);
            float s2 = fsetge(xv, thr[4]) + fsetge(xv, thr[5]);
            float s3 = fsetge(xv, thr[6]) + fsetge(xv, thr[7]);
            float kf = fmaf(fsetge(xv, thr[8]), -8.0f, (s0 + s1) + (s2 + s3));
            const int idx = __float2int_rz(kf) * DD + d;

            const float4 A  = sTA[idx];   // invW, -cw*invW, cumH, H
            const float4 Bv = sTB[idx];   // delta, d0, d1, e

            const float theta = fmaf(xv, A.x, A.y);
            const float omt   = 1.0f - theta;
            const float th2   = theta * theta;
            const float t1m   = theta * omt;
            const float omt2  = omt * omt;
            const float t1m2  = t1m + t1m;

            const float num    = A.w * fmaf(Bv.x, th2, Bv.y * t1m);
            const float den    = fmaf(Bv.w, t1m, Bv.x);
            const float invden = __fdividef(1.0f, den);
            const float uo     = fmaf(num, invden, A.z);

            const float inner = fmaf(Bv.z, th2, fmaf(Bv.x, t1m2, Bv.y * omt2));
            const float dnum  = (Bv.x * Bv.x) * inner;
            lads[e] = __logf(dnum * (invden * invden));

            pu[e ? DD : 0] = uo;
        }

        // 3-step butterflies: lanes 0..3 hold 4 group sums per row
        float la = lads[0], lb = lads[1];
        la += __shfl_xor_sync(0xffffffffu, la, 16);
        lb += __shfl_xor_sync(0xffffffffu, lb, 16);
        la += __shfl_xor_sync(0xffffffffu, la, 8);
        lb += __shfl_xor_sync(0xffffffffu, lb, 8);
        la += __shfl_xor_sync(0xffffffffu, la, 4);
        lb += __shfl_xor_sync(0xffffffffu, lb, 4);
        if (lane < 4) {
            PART(team, wslot, pi, 0, lane) = la;
            PART(team, wslot, pi, 1, lane) = lb;
        }

        px += STEP;
        pu += STEP;
        xa = xa2;
        xb = xb2;
    }
    __syncthreads();

    // ---- combine 16 partials per row (4 warps x 4 lane-groups) ----
    if (tid < TEAMS * MAXP * 2) {
        const int tm   = tid / (MAXP * 2);
        const int rem  = tid - tm * (MAXP * 2);
        const int ppi  = rem >> 1;
        const int half = rem & 1;
        const int gp   = blockIdx.x * TEAMS + tm + ppi * NSP;
        if (gp < NPAIRS) {
            float v = 0.f;
            #pragma unroll
            for (int w = 0; w < 4; w++) {
                v += (PART(tm, w, ppi, half, 0) + PART(tm, w, ppi, half, 1)) +
                     (PART(tm, w, ppi, half, 2) + PART(tm, w, ppi, half, 3));
            }
            ldout[2 * gp + half] = v;
        }
    }
}

extern "C" void kernel_launch(void* const* d_in, const int* in_sizes, int n_in,
                              void* d_out, int out_size) {
    const float* x  = (const float*)d_in[0];
    const float* uw = (const float*)d_in[1];
    const float* uh = (const float*)d_in[2];
    const float* ud = (const float*)d_in[3];
    float* out = (float*)d_out;

    spline_kernel<<<GRIDB, BLOCK>>>(x, uw, uh, ud, out, out + (size_t)BB * DD);
}

// round 12
// speedup vs baseline: 1.0748x; 1.0748x over previous
#include <cuda_runtime.h>

// ComponentWiseSpline: rational-quadratic spline flow, forward + log|det J|.
// B=65536 rows, D=128 dims, K=8 interior bins.
// R12: R10 config (512 thr, launch_bounds(512,3), grid 444=148x3, 4-warp
//      teams, FSET+FADD search, depth-1 prefetch) + 9-slot identity-shared
//      table (-8 FFMA trick) + 3-step butterfly reduction + smem overlay.

#define BB 65536
#define DD 128
#define KK 8
#define NSLOT 9                          // identity | 8 interior
#define NPAIRS (BB / 2)                  // 32768 row-pairs
#define BLOCK 512
#define TEAMS 4                          // 4-warp teams per block
#define GRIDB 444                        // 148 SMs * 3 blocks
#define NSP (GRIDB * TEAMS)              // 1776 row-pair streams
#define MAXP ((NPAIRS + NSP - 1) / NSP)  // 19

// overlay: thresholds (staging, 9*128=1152 floats) then partials (2432 floats)
#define AUXN (TEAMS * 4 * MAXP * 2 * 4)  // 2432 floats = 9.5 KB
#define PART(t, w, pi, r, q) \
    sAux[((((t) * 4 + (w)) * MAXP + (pi)) * 2 + (r)) * 4 + (q)]

__device__ __forceinline__ float fsetge(float a, float b) {
    float r;
    asm("set.ge.f32.f32 %0, %1, %2;" : "=f"(r) : "f"(a), "f"(b));
    return r;
}

__global__ void __launch_bounds__(BLOCK, 3)
spline_kernel(const float* __restrict__ x,
              const float* __restrict__ uw,
              const float* __restrict__ uh,
              const float* __restrict__ ud,
              float* __restrict__ uout,
              float* __restrict__ ldout) {
    __shared__ float4 sTA[NSLOT * DD];   // 18 KB {invW, -cw*invW, cumH, H}
    __shared__ float4 sTB[NSLOT * DD];   // 18 KB {delta, d0, d1, e}
    __shared__ float  sAux[AUXN];        // 9.5 KB overlay

    const int tid  = threadIdx.x;
    const int lane = tid & 31;
    const int warp = tid >> 5;       // 0..15
    const int team = warp >> 2;      // 0..3
    const int wslot = warp & 3;      // 0..3
    const int d = (wslot << 5) + lane;

    // ---- per-block table build: thread dd (<128) builds dim dd ----
    if (tid < DD) {
        const float BOUND = 3.0f;
        const float MINW = 1e-3f, MINH = 1e-3f, MIND = 1e-3f, EPS = 1e-6f;
        const int dd = tid;

        float w[KK], h[KK];
        float m = -1e30f;
        #pragma unroll
        for (int k = 0; k < KK; k++) { w[k] = uw[dd * KK + k]; m = fmaxf(m, w[k]); }
        float s = 0.f;
        #pragma unroll
        for (int k = 0; k < KK; k++) { w[k] = expf(w[k] - m); s += w[k]; }
        float invs = 1.0f / s;
        #pragma unroll
        for (int k = 0; k < KK; k++) w[k] = MINW + (1.0f - MINW * KK) * (w[k] * invs);

        m = -1e30f;
        #pragma unroll
        for (int k = 0; k < KK; k++) { h[k] = uh[dd * KK + k]; m = fmaxf(m, h[k]); }
        s = 0.f;
        #pragma unroll
        for (int k = 0; k < KK; k++) { h[k] = expf(h[k] - m); s += h[k]; }
        invs = 1.0f / s;
        #pragma unroll
        for (int k = 0; k < KK; k++) h[k] = MINH + (1.0f - MINH * KK) * (h[k] * invs);

        float cw[KK + 1], ch[KK + 1];
        cw[0] = -BOUND; ch[0] = -BOUND;
        float accw = 0.f, acch = 0.f;
        #pragma unroll
        for (int k = 1; k < KK; k++) {
            accw += w[k - 1]; cw[k] = fmaf(2.0f * BOUND, accw, -BOUND);
            acch += h[k - 1]; ch[k] = fmaf(2.0f * BOUND, acch, -BOUND);
        }
        cw[KK] = BOUND; ch[KK] = BOUND;

        float dv[KK + 1];
        dv[0] = 1.0f - MIND; dv[KK] = 1.0f - MIND;
        #pragma unroll
        for (int k = 1; k < KK; k++) {
            float v = ud[dd * (KK - 1) + (k - 1)];
            dv[k] = MIND + fmaxf(v, 0.0f) + log1pf(expf(-fabsf(v)));
        }

        // interior bins k -> slot k+1 (slots 1..8)
        #pragma unroll
        for (int k = 0; k < KK; k++) {
            float W = cw[k + 1] - cw[k];
            float H = ch[k + 1] - ch[k];
            float invW = 1.0f / W;
            float del  = H * invW;
            sTA[(k + 1) * DD + dd] = make_float4(invW, -cw[k] * invW, ch[k], H);
            sTB[(k + 1) * DD + dd] = make_float4(del, dv[k], dv[k + 1],
                                                 dv[k] + dv[k + 1] - 2.0f * del);
        }
        // identity slot 0 (both tails): u = x, lad = 0
        sTA[0 * DD + dd] = make_float4(1.0f, 0.0f, 0.0f, 1.0f);
        sTB[0 * DD + dd] = make_float4(1.0f, 1.0f, 1.0f, 0.0f);

        // thresholds into overlay region
        sAux[0 * DD + dd] = -3.0f;
        #pragma unroll
        for (int t = 1; t < 8; t++) sAux[t * DD + dd] = cw[t] + EPS;
        sAux[8 * DD + dd] = __int_as_float(0x40400001);   // nextafter(3.0f)
    }
    __syncthreads();

    // ---- this lane's 9 thresholds into registers ----
    float thr[9];
    #pragma unroll
    for (int j = 0; j < 9; j++) thr[j] = sAux[j * DD + d];
    __syncthreads();   // overlay handoff: thresholds read; partials may write

    const int S = blockIdx.x * TEAMS + team;        // stream id, 0..NSP-1
    const int cnt = (NPAIRS - S + NSP - 1) / NSP;   // 18 or 19 pairs
    const size_t STEP = (size_t)NSP * 256;

    const float* px = x + (size_t)S * 256 + d;
    float*       pu = uout + (size_t)S * 256 + d;
    float xa = px[0];
    float xb = px[DD];

    for (int pi = 0; pi < cnt; pi++) {
        float xa2, xb2;
        if (pi < cnt - 1) {
            xa2 = __ldg(px + STEP);
            xb2 = __ldg(px + STEP + DD);
        }

        float lads[2];
        float xin[2] = {xa, xb};
        #pragma unroll
        for (int e = 0; e < 2; e++) {
            const float xv = xin[e];
            // slot = 1 + bin interior; 0 for both tails (-8 on the exit set)
            float s0 = fsetge(xv, thr[0]) + fsetge(xv, thr[1]);
            float s1 = fsetge(xv, thr[2]) + fsetge(xv, thr[3]);
            float s2 = fsetge(xv, thr[4]) + fsetge(xv, thr[5]);
            float s3 = fsetge(xv, thr[6]) + fsetge(xv, thr[7]);
            float kf = fmaf(fsetge(xv, thr[8]), -8.0f, (s0 + s1) + (s2 + s3));
            const int idx = __float2int_rz(kf) * DD + d;

            const float4 A  = sTA[idx];   // invW, -cw*invW, cumH, H
            const float4 Bv = sTB[idx];   // delta, d0, d1, e

            const float theta = fmaf(xv, A.x, A.y);
            const float omt   = 1.0f - theta;
            const float th2   = theta * theta;
            const float t1m   = theta * omt;
            const float omt2  = omt * omt;
            const float t1m2  = t1m + t1m;

            const float num    = A.w * fmaf(Bv.x, th2, Bv.y * t1m);
            const float den    = fmaf(Bv.w, t1m, Bv.x);
            const float invden = __fdividef(1.0f, den);
            const float uo     = fmaf(num, invden, A.z);

            const float inner = fmaf(Bv.z, th2, fmaf(Bv.x, t1m2, Bv.y * omt2));
            const float dnum  = (Bv.x * Bv.x) * inner;
            lads[e] = __logf(dnum * (invden * invden));

            pu[e ? DD : 0] = uo;
        }

        // 3-step butterflies: lanes 0..3 hold the 4 group sums per row
        float la = lads[0], lb = lads[1];
        la += __shfl_xor_sync(0xffffffffu, la, 16);
        lb += __shfl_xor_sync(0xffffffffu, lb, 16);
        la += __shfl_xor_sync(0xffffffffu, la, 8);
        lb += __shfl_xor_sync(0xffffffffu, lb, 8);
        la += __shfl_xor_sync(0xffffffffu, la, 4);
        lb += __shfl_xor_sync(0xffffffffu, lb, 4);
        if (lane < 4) {
            PART(team, wslot, pi, 0, lane) = la;
            PART(team, wslot, pi, 1, lane) = lb;
        }

        px += STEP;
        pu += STEP;
        xa = xa2;
        xb = xb2;
    }
    __syncthreads();

    // ---- combine 16 partials per row (4 warps x 4 lane-groups) ----
    if (tid < TEAMS * MAXP * 2) {
        const int tm   = tid / (MAXP * 2);
        const int rem  = tid - tm * (MAXP * 2);
        const int ppi  = rem >> 1;
        const int half = rem & 1;
        const int gp   = blockIdx.x * TEAMS + tm + ppi * NSP;
        if (gp < NPAIRS) {
            float v = 0.f;
            #pragma unroll
            for (int w = 0; w < 4; w++) {
                v += (PART(tm, w, ppi, half, 0) + PART(tm, w, ppi, half, 1)) +
                     (PART(tm, w, ppi, half, 2) + PART(tm, w, ppi, half, 3));
            }
            ldout[2 * gp + half] = v;
        }
    }
}

extern "C" void kernel_launch(void* const* d_in, const int* in_sizes, int n_in,
                              void* d_out, int out_size) {
    const float* x  = (const float*)d_in[0];
    const float* uw = (const float*)d_in[1];
    const float* uh = (const float*)d_in[2];
    const float* ud = (const float*)d_in[3];
    float* out = (float*)d_out;

    spline_kernel<<<GRIDB, BLOCK>>>(x, uw, uh, ud, out, out + (size_t)BB * DD);
}

// round 13
// speedup vs baseline: 1.1902x; 1.1074x over previous
#include <cuda_runtime.h>

// ComponentWiseSpline: rational-quadratic spline flow, forward + log|det J|.
// B=65536 rows, D=128 dims, K=8 interior bins.
// R13: 4 elems/lane/iter (lane owns 2 adjacent dims x 2 rows in flight),
//      float2 I/O, 9-slot identity-shared table (-8 FFMA trick), 3-step
//      butterfly, smem overlay, 384-thr blocks (reg cap 56), grid 444=148x3.

#define BB 65536
#define DD 128
#define KK 8
#define NSLOT 9                          // identity | 8 interior
#define NPAIRS (BB / 2)                  // 32768 row-pairs
#define BLOCK 384
#define TEAMS 6                          // 2-warp teams per block
#define GRIDB 444                        // 148 SMs * 3 blocks
#define NSP (GRIDB * TEAMS)              // 2664 row-pair streams
#define MAXP ((NPAIRS + NSP - 1) / NSP)  // 13

// overlay: thresholds staging (9*128=1152 floats), then partials (1248 floats)
#define AUXN (TEAMS * 2 * MAXP * 2 * 4)  // 1248 floats
#define PART(t, h, pi, r, q) \
    sAux[((((t) * 2 + (h)) * MAXP + (pi)) * 2 + (r)) * 4 + (q)]

__device__ __forceinline__ float fsetge(float a, float b) {
    float r;
    asm("set.ge.f32.f32 %0, %1, %2;" : "=f"(r) : "f"(a), "f"(b));
    return r;
}

__global__ void __launch_bounds__(BLOCK, 3)
spline_kernel(const float* __restrict__ x,
              const float* __restrict__ uw,
              const float* __restrict__ uh,
              const float* __restrict__ ud,
              float* __restrict__ uout,
              float* __restrict__ ldout) {
    __shared__ float4 sTA[NSLOT * DD];   // 18 KB {invW, -cw*invW, cumH, H}
    __shared__ float4 sTB[NSLOT * DD];   // 18 KB {delta, d0, d1, e}
    __shared__ float  sAux[AUXN];        // 4.9 KB overlay

    const int tid  = threadIdx.x;
    const int lane = tid & 31;
    const int warp = tid >> 5;       // 0..11
    const int team = warp >> 1;      // 0..5
    const int half = warp & 1;       // which 64-dim half of the row

    // ---- per-block table build: thread dd (<128) builds dim dd ----
    if (tid < DD) {
        const float BOUND = 3.0f;
        const float MINW = 1e-3f, MINH = 1e-3f, MIND = 1e-3f, EPS = 1e-6f;
        const int dd = tid;

        float w[KK], h[KK];
        float m = -1e30f;
        #pragma unroll
        for (int k = 0; k < KK; k++) { w[k] = uw[dd * KK + k]; m = fmaxf(m, w[k]); }
        float s = 0.f;
        #pragma unroll
        for (int k = 0; k < KK; k++) { w[k] = expf(w[k] - m); s += w[k]; }
        float invs = 1.0f / s;
        #pragma unroll
        for (int k = 0; k < KK; k++) w[k] = MINW + (1.0f - MINW * KK) * (w[k] * invs);

        m = -1e30f;
        #pragma unroll
        for (int k = 0; k < KK; k++) { h[k] = uh[dd * KK + k]; m = fmaxf(m, h[k]); }
        s = 0.f;
        #pragma unroll
        for (int k = 0; k < KK; k++) { h[k] = expf(h[k] - m); s += h[k]; }
        invs = 1.0f / s;
        #pragma unroll
        for (int k = 0; k < KK; k++) h[k] = MINH + (1.0f - MINH * KK) * (h[k] * invs);

        float cw[KK + 1], ch[KK + 1];
        cw[0] = -BOUND; ch[0] = -BOUND;
        float accw = 0.f, acch = 0.f;
        #pragma unroll
        for (int k = 1; k < KK; k++) {
            accw += w[k - 1]; cw[k] = fmaf(2.0f * BOUND, accw, -BOUND);
            acch += h[k - 1]; ch[k] = fmaf(2.0f * BOUND, acch, -BOUND);
        }
        cw[KK] = BOUND; ch[KK] = BOUND;

        float dv[KK + 1];
        dv[0] = 1.0f - MIND; dv[KK] = 1.0f - MIND;
        #pragma unroll
        for (int k = 1; k < KK; k++) {
            float v = ud[dd * (KK - 1) + (k - 1)];
            dv[k] = MIND + fmaxf(v, 0.0f) + log1pf(expf(-fabsf(v)));
        }

        // slot remap: dim dd = hh*64 + 2*pos + c  ->  slot hh*64 + c*32 + pos
        const int hh  = dd >> 6;
        const int rem = dd & 63;
        const int s_slot = (hh << 6) + ((rem & 1) << 5) + (rem >> 1);

        // interior bins k -> slot k+1 (slots 1..8)
        #pragma unroll
        for (int k = 0; k < KK; k++) {
            float W = cw[k + 1] - cw[k];
            float H = ch[k + 1] - ch[k];
            float invW = 1.0f / W;
            float del  = H * invW;
            sTA[(k + 1) * DD + s_slot] = make_float4(invW, -cw[k] * invW, ch[k], H);
            sTB[(k + 1) * DD + s_slot] = make_float4(del, dv[k], dv[k + 1],
                                                     dv[k] + dv[k + 1] - 2.0f * del);
        }
        // identity slot 0 (both tails): u = x, lad = 0
        sTA[0 * DD + s_slot] = make_float4(1.0f, 0.0f, 0.0f, 1.0f);
        sTB[0 * DD + s_slot] = make_float4(1.0f, 1.0f, 1.0f, 0.0f);

        // thresholds into overlay region
        sAux[0 * DD + s_slot] = -3.0f;
        #pragma unroll
        for (int t = 1; t < 8; t++) sAux[t * DD + s_slot] = cw[t] + EPS;
        sAux[8 * DD + s_slot] = __int_as_float(0x40400001);   // nextafter(3.0f)
    }
    __syncthreads();

    // ---- this lane's 2x9 thresholds into registers ----
    const int slotc[2] = {(half << 6) + lane, (half << 6) + 32 + lane};
    float thr[2][9];
    #pragma unroll
    for (int c = 0; c < 2; c++) {
        #pragma unroll
        for (int j = 0; j < 9; j++) thr[c][j] = sAux[j * DD + slotc[c]];
    }
    __syncthreads();   // overlay handoff: thresholds read; partials may write

    const int S = blockIdx.x * TEAMS + team;        // stream id, 0..NSP-1
    const int cnt = (NPAIRS - S + NSP - 1) / NSP;   // 12 or 13 pairs
    const size_t STEP = (size_t)NSP * 256;
    const int coloff = (half << 6) + (lane << 1);

    const float* px = x + (size_t)S * 256 + coloff;
    float*       pu = uout + (size_t)S * 256 + coloff;
    float2 xA = *reinterpret_cast<const float2*>(px);        // row 2p
    float2 xB = *reinterpret_cast<const float2*>(px + DD);   // row 2p+1

    for (int pi = 0; pi < cnt; pi++) {
        float2 xA2, xB2;
        if (pi < cnt - 1) {
            xA2 = *reinterpret_cast<const float2*>(px + STEP);
            xB2 = *reinterpret_cast<const float2*>(px + STEP + DD);
        }

        float uo[4], lads[2] = {0.f, 0.f};
        float xin[4] = {xA.x, xA.y, xB.x, xB.y};
        #pragma unroll
        for (int e = 0; e < 4; e++) {
            const int c = e & 1;          // which of the lane's 2 dims
            const float xv = xin[e];
            // slot = 1 + interior bin; 0 for both tails (-8 on the exit set)
            float s0 = fsetge(xv, thr[c][0]) + fsetge(xv, thr[c][1]);
            float s1 = fsetge(xv, thr[c][2]) + fsetge(xv, thr[c][3]);
            float s2 = fsetge(xv, thr[c][4]) + fsetge(xv, thr[c][5]);
            float s3 = fsetge(xv, thr[c][6]) + fsetge(xv, thr[c][7]);
            float kf = fmaf(fsetge(xv, thr[c][8]), -8.0f,
                            (s0 + s1) + (s2 + s3));
            const int idx = __float2int_rz(kf) * DD + slotc[c];

            const float4 A  = sTA[idx];   // invW, -cw*invW, cumH, H
            const float4 Bv = sTB[idx];   // delta, d0, d1, e

            const float theta = fmaf(xv, A.x, A.y);
            const float omt   = 1.0f - theta;
            const float th2   = theta * theta;
            const float t1m   = theta * omt;
            const float omt2  = omt * omt;
            const float t1m2  = t1m + t1m;

            const float num    = A.w * fmaf(Bv.x, th2, Bv.y * t1m);
            const float den    = fmaf(Bv.w, t1m, Bv.x);
            const float invden = __fdividef(1.0f, den);
            uo[e] = fmaf(num, invden, A.z);

            const float inner = fmaf(Bv.z, th2, fmaf(Bv.x, t1m2, Bv.y * omt2));
            const float dnum  = (Bv.x * Bv.x) * inner;
            lads[e >> 1] += __logf(dnum * (invden * invden));
        }

        *reinterpret_cast<float2*>(pu)      = make_float2(uo[0], uo[1]);
        *reinterpret_cast<float2*>(pu + DD) = make_float2(uo[2], uo[3]);

        // 3-step butterflies: lanes 0..3 hold the 4 group sums per row
        float la = lads[0], lb = lads[1];
        la += __shfl_xor_sync(0xffffffffu, la, 16);
        lb += __shfl_xor_sync(0xffffffffu, lb, 16);
        la += __shfl_xor_sync(0xffffffffu, la, 8);
        lb += __shfl_xor_sync(0xffffffffu, lb, 8);
        la += __shfl_xor_sync(0xffffffffu, la, 4);
        lb += __shfl_xor_sync(0xffffffffu, lb, 4);
        if (lane < 4) {
            PART(team, half, pi, 0, lane) = la;
            PART(team, half, pi, 1, lane) = lb;
        }

        px += STEP;
        pu += STEP;
        xA = xA2;
        xB = xB2;
    }
    __syncthreads();

    // ---- combine 8 partials per row (2 warps x 4 lane-groups) ----
    if (tid < TEAMS * MAXP * 2) {
        const int tm  = tid / (MAXP * 2);
        const int rem = tid - tm * (MAXP * 2);
        const int ppi = rem >> 1;
        const int rb  = rem & 1;
        const int gp  = blockIdx.x * TEAMS + tm + ppi * NSP;
        if (gp < NPAIRS) {
            float v = 0.f;
            #pragma unroll
            for (int hh = 0; hh < 2; hh++)
                v += (PART(tm, hh, ppi, rb, 0) + PART(tm, hh, ppi, rb, 1)) +
                     (PART(tm, hh, ppi, rb, 2) + PART(tm, hh, ppi, rb, 3));
            ldout[2 * gp + rb] = v;
        }
    }
}

extern "C" void kernel_launch(void* const* d_in, const int* in_sizes, int n_in,
                              void* d_out, int out_size) {
    const float* x  = (const float*)d_in[0];
    const float* uw = (const float*)d_in[1];
    const float* uh = (const float*)d_in[2];
    const float* ud = (const float*)d_in[3];
    float* out = (float*)d_out;

    spline_kernel<<<GRIDB, BLOCK>>>(x, uw, uh, ud, out, out + (size_t)BB * DD);
}

// round 14
// speedup vs baseline: 1.2796x; 1.0751x over previous
#include <cuda_runtime.h>

// ComponentWiseSpline: rational-quadratic spline flow, forward + log|det J|.
// B=65536 rows, D=128 dims, K=8 interior bins.
// R14: 8 elems/lane/iter (2 adjacent dims x 4 rows in flight), log-product
//      (1 __logf per row per iter), 9-slot identity-shared table, 3-step
//      butterfly + float4 partial park, 296 blocks x 512 thr (reg cap 64).

#define BB 65536
#define DD 128
#define KK 8
#define NSLOT 9                          // identity | 8 interior
#define NQ (BB / 4)                      // 16384 row-quads
#define BLOCK 512
#define TEAMS 8                          // 2-warp teams per block
#define GRIDB 296                        // 148 SMs * 2 blocks
#define NSQ (GRIDB * TEAMS)              // 2368 quad-streams
#define MAXQ ((NQ + NSQ - 1) / NSQ)      // 7

// overlay: thresholds staging (1152 floats), then partials (1792 floats)
#define AUXN (TEAMS * 2 * MAXQ * 4 * 4)  // 1792 floats = 7 KB
#define PARTBASE(t, h, i) ((((t) * 2 + (h)) * MAXQ + (i)) * 16)

__device__ __forceinline__ float fsetge(float a, float b) {
    float r;
    asm("set.ge.f32.f32 %0, %1, %2;" : "=f"(r) : "f"(a), "f"(b));
    return r;
}

__global__ void __launch_bounds__(BLOCK, 2)
spline_kernel(const float* __restrict__ x,
              const float* __restrict__ uw,
              const float* __restrict__ uh,
              const float* __restrict__ ud,
              float* __restrict__ uout,
              float* __restrict__ ldout) {
    __shared__ float4 sTA[NSLOT * DD];   // 18 KB {invW, -cw*invW, cumH, H}
    __shared__ float4 sTB[NSLOT * DD];   // 18 KB {delta, d0, d1, e}
    __shared__ float  sAux[AUXN];        // 7 KB overlay

    const int tid  = threadIdx.x;
    const int lane = tid & 31;
    const int warp = tid >> 5;       // 0..15
    const int team = warp >> 1;      // 0..7
    const int half = warp & 1;       // which 64-dim half of the row

    // ---- per-block table build: thread dd (<128) builds dim dd ----
    if (tid < DD) {
        const float BOUND = 3.0f;
        const float MINW = 1e-3f, MINH = 1e-3f, MIND = 1e-3f, EPS = 1e-6f;
        const int dd = tid;

        float w[KK], h[KK];
        float m = -1e30f;
        #pragma unroll
        for (int k = 0; k < KK; k++) { w[k] = uw[dd * KK + k]; m = fmaxf(m, w[k]); }
        float s = 0.f;
        #pragma unroll
        for (int k = 0; k < KK; k++) { w[k] = expf(w[k] - m); s += w[k]; }
        float invs = 1.0f / s;
        #pragma unroll
        for (int k = 0; k < KK; k++) w[k] = MINW + (1.0f - MINW * KK) * (w[k] * invs);

        m = -1e30f;
        #pragma unroll
        for (int k = 0; k < KK; k++) { h[k] = uh[dd * KK + k]; m = fmaxf(m, h[k]); }
        s = 0.f;
        #pragma unroll
        for (int k = 0; k < KK; k++) { h[k] = expf(h[k] - m); s += h[k]; }
        invs = 1.0f / s;
        #pragma unroll
        for (int k = 0; k < KK; k++) h[k] = MINH + (1.0f - MINH * KK) * (h[k] * invs);

        float cw[KK + 1], ch[KK + 1];
        cw[0] = -BOUND; ch[0] = -BOUND;
        float accw = 0.f, acch = 0.f;
        #pragma unroll
        for (int k = 1; k < KK; k++) {
            accw += w[k - 1]; cw[k] = fmaf(2.0f * BOUND, accw, -BOUND);
            acch += h[k - 1]; ch[k] = fmaf(2.0f * BOUND, acch, -BOUND);
        }
        cw[KK] = BOUND; ch[KK] = BOUND;

        float dv[KK + 1];
        dv[0] = 1.0f - MIND; dv[KK] = 1.0f - MIND;
        #pragma unroll
        for (int k = 1; k < KK; k++) {
            float v = ud[dd * (KK - 1) + (k - 1)];
            dv[k] = MIND + fmaxf(v, 0.0f) + log1pf(expf(-fabsf(v)));
        }

        // slot remap: dim dd = hh*64 + 2*pos + c  ->  slot hh*64 + c*32 + pos
        const int hh  = dd >> 6;
        const int rem = dd & 63;
        const int s_slot = (hh << 6) + ((rem & 1) << 5) + (rem >> 1);

        // interior bins k -> slot k+1 (slots 1..8)
        #pragma unroll
        for (int k = 0; k < KK; k++) {
            float W = cw[k + 1] - cw[k];
            float H = ch[k + 1] - ch[k];
            float invW = 1.0f / W;
            float del  = H * invW;
            sTA[(k + 1) * DD + s_slot] = make_float4(invW, -cw[k] * invW, ch[k], H);
            sTB[(k + 1) * DD + s_slot] = make_float4(del, dv[k], dv[k + 1],
                                                     dv[k] + dv[k + 1] - 2.0f * del);
        }
        // identity slot 0 (both tails): u = x, derivative = 1 (lad contrib 0)
        sTA[0 * DD + s_slot] = make_float4(1.0f, 0.0f, 0.0f, 1.0f);
        sTB[0 * DD + s_slot] = make_float4(1.0f, 1.0f, 1.0f, 0.0f);

        // thresholds into overlay region
        sAux[0 * DD + s_slot] = -3.0f;
        #pragma unroll
        for (int t = 1; t < 8; t++) sAux[t * DD + s_slot] = cw[t] + EPS;
        sAux[8 * DD + s_slot] = __int_as_float(0x40400001);   // nextafter(3.0f)
    }
    __syncthreads();

    // ---- this lane's 2x9 thresholds into registers ----
    const int slotc0 = (half << 6) + lane;
    const int slotc1 = slotc0 + 32;
    float thr[2][9];
    #pragma unroll
    for (int j = 0; j < 9; j++) thr[0][j] = sAux[j * DD + slotc0];
    #pragma unroll
    for (int j = 0; j < 9; j++) thr[1][j] = sAux[j * DD + slotc1];
    __syncthreads();   // overlay handoff: thresholds read; partials may write

    const int S = blockIdx.x * TEAMS + team;     // quad-stream id, 0..NSQ-1
    const int cnt = (NQ - S + NSQ - 1) / NSQ;    // 6 or 7 quads
    const size_t STEP = (size_t)NSQ * 512;       // floats per stream step
    const int coloff = (half << 6) + (lane << 1);

    const float* px = x + (size_t)S * 512 + coloff;
    float*       pu = uout + (size_t)S * 512 + coloff;
    float2 xq[4], xn[4];
    #pragma unroll
    for (int r = 0; r < 4; r++)
        xq[r] = *reinterpret_cast<const float2*>(px + r * DD);

    for (int pi = 0; pi < cnt; pi++) {
        if (pi < cnt - 1) {
            #pragma unroll
            for (int r = 0; r < 4; r++)
                xn[r] = *reinterpret_cast<const float2*>(px + STEP + r * DD);
        }

        float P[4];
        #pragma unroll
        for (int r = 0; r < 4; r++) {
            float xin[2] = {xq[r].x, xq[r].y};
            float uo2[2];
            float prod = 1.0f;
            #pragma unroll
            for (int c = 0; c < 2; c++) {
                const float xv = xin[c];
                // slot = 1 + interior bin; 0 for both tails (-8 on exit set)
                float s0 = fsetge(xv, thr[c][0]) + fsetge(xv, thr[c][1]);
                float s1 = fsetge(xv, thr[c][2]) + fsetge(xv, thr[c][3]);
                float s2 = fsetge(xv, thr[c][4]) + fsetge(xv, thr[c][5]);
                float s3 = fsetge(xv, thr[c][6]) + fsetge(xv, thr[c][7]);
                float kf = fmaf(fsetge(xv, thr[c][8]), -8.0f,
                                (s0 + s1) + (s2 + s3));
                const int idx = __float2int_rz(kf) * DD +
                                (c ? slotc1 : slotc0);

                const float4 A  = sTA[idx];   // invW, -cw*invW, cumH, H
                const float4 Bv = sTB[idx];   // delta, d0, d1, e

                const float theta = fmaf(xv, A.x, A.y);
                const float omt   = 1.0f - theta;
                const float th2   = theta * theta;
                const float t1m   = theta * omt;
                const float omt2  = omt * omt;
                const float t1m2  = t1m + t1m;

                const float num    = A.w * fmaf(Bv.x, th2, Bv.y * t1m);
                const float den    = fmaf(Bv.w, t1m, Bv.x);
                const float invden = __fdividef(1.0f, den);
                uo2[c] = fmaf(num, invden, A.z);

                const float inner = fmaf(Bv.z, th2,
                                         fmaf(Bv.x, t1m2, Bv.y * omt2));
                const float dnum  = (Bv.x * Bv.x) * inner;
                prod *= dnum * (invden * invden);   // du/dx for this elem
            }
            P[r] = prod;
            *reinterpret_cast<float2*>(pu + r * DD) =
                make_float2(uo2[0], uo2[1]);
        }

        // one log per row (product of the lane's 2 derivative factors)
        float la = __logf(P[0]);
        float lb = __logf(P[1]);
        float lc = __logf(P[2]);
        float ld = __logf(P[3]);

        // 3-step butterflies: lanes 0..3 hold 4-lane-group sums
        #pragma unroll
        for (int off = 16; off >= 4; off >>= 1) {
            la += __shfl_xor_sync(0xffffffffu, la, off);
            lb += __shfl_xor_sync(0xffffffffu, lb, off);
            lc += __shfl_xor_sync(0xffffffffu, lc, off);
            ld += __shfl_xor_sync(0xffffffffu, ld, off);
        }
        if (lane < 4) {
            float4* p = reinterpret_cast<float4*>(
                &sAux[PARTBASE(team, half, pi) + lane * 4]);
            *p = make_float4(la, lb, lc, ld);
        }

        px += STEP;
        pu += STEP;
        #pragma unroll
        for (int r = 0; r < 4; r++) xq[r] = xn[r];
    }
    __syncthreads();

    // ---- combine 8 partials per row (2 halves x 4 lane-groups) ----
    if (tid < TEAMS * MAXQ * 4) {
        const int tm  = tid / (MAXQ * 4);
        const int rem = tid - tm * (MAXQ * 4);
        const int qi  = rem >> 2;
        const int rb  = rem & 3;
        const int gq  = blockIdx.x * TEAMS + tm + qi * NSQ;
        if (gq < NQ) {
            float v = 0.f;
            #pragma unroll
            for (int hh = 0; hh < 2; hh++) {
                const int base = PARTBASE(tm, hh, qi);
                v += (sAux[base + 0 * 4 + rb] + sAux[base + 1 * 4 + rb]) +
                     (sAux[base + 2 * 4 + rb] + sAux[base + 3 * 4 + rb]);
            }
            ldout[4 * gq + rb] = v;
        }
    }
}

extern "C" void kernel_launch(void* const* d_in, const int* in_sizes, int n_in,
                              void* d_out, int out_size) {
    const float* x  = (const float*)d_in[0];
    const float* uw = (const float*)d_in[1];
    const float* uh = (const float*)d_in[2];
    const float* ud = (const float*)d_in[3];
    float* out = (float*)d_out;

    spline_kernel<<<GRIDB, BLOCK>>>(x, uw, uh, ud, out, out + (size_t)BB * DD);
}